// round 11
// baseline (speedup 1.0000x reference)
#include <cuda_runtime.h>
#include <cuda_bf16.h>
#include <cstdint>

#define NRES 512
#define DCH  128
#define NPOS (NRES*NRES)

// Scratch (device globals — no runtime allocation allowed)
__device__ float g_gate [(size_t)NPOS * DCH];
__device__ float g_pret [(size_t)NPOS * DCH];        // [d][i][k]
__device__ __nv_bfloat16 g_Xh[(size_t)NPOS * DCH];   // LN(x) split, [pos][d]
__device__ __nv_bfloat16 g_Xl[(size_t)NPOS * DCH];
__device__ __nv_bfloat16 g_Lh[(size_t)DCH * NPOS];   // [d][i][j]; later pre-split [pos][d]
__device__ __nv_bfloat16 g_Ll[(size_t)DCH * NPOS];
__device__ __nv_bfloat16 g_Rh[(size_t)DCH * NPOS];   // [d][k][j]
__device__ __nv_bfloat16 g_Rl[(size_t)DCH * NPOS];
__device__ __nv_bfloat16 g_Wth[6 * DCH * DCH];       // W^T hi, [widx][n][k]
__device__ __nv_bfloat16 g_Wtl[6 * DCH * DCH];       // W^T lo

__device__ __forceinline__ float fsig(float x) { return 1.0f / (1.0f + __expf(-x)); }

__device__ __forceinline__ void cp16(void* s, const void* g) {
    unsigned sa = (unsigned)__cvta_generic_to_shared(s);
    asm volatile("cp.async.cg.shared.global [%0], [%1], 16;" :: "r"(sa), "l"(g));
}

// ---- mma.sync / ldmatrix (sm_80-class PTX: compiles on plain sm_103) ------
__device__ __forceinline__ void ldsm_x4(uint32_t* r, uint32_t addr) {
    asm volatile("ldmatrix.sync.aligned.m8n8.x4.shared.b16 {%0,%1,%2,%3}, [%4];"
        : "=r"(r[0]), "=r"(r[1]), "=r"(r[2]), "=r"(r[3]) : "r"(addr));
}
__device__ __forceinline__ void ldsm_x2(uint32_t* r, uint32_t addr) {
    asm volatile("ldmatrix.sync.aligned.m8n8.x2.shared.b16 {%0,%1}, [%2];"
        : "=r"(r[0]), "=r"(r[1]) : "r"(addr));
}
__device__ __forceinline__ void mma16816(float* c, const uint32_t* a, const uint32_t* b) {
    asm volatile("mma.sync.aligned.m16n8k16.row.col.f32.bf16.bf16.f32 "
        "{%0,%1,%2,%3}, {%4,%5,%6,%7}, {%8,%9}, {%0,%1,%2,%3};"
        : "+f"(c[0]), "+f"(c[1]), "+f"(c[2]), "+f"(c[3])
        : "r"(a[0]), "r"(a[1]), "r"(a[2]), "r"(a[3]), "r"(b[0]), "r"(b[1]));
}
// C += Ah*Bh + Ah*Bl + Al*Bh   (bf16 hi/lo split product)
__device__ __forceinline__ void mma3(float* c, const uint32_t* aH, const uint32_t* aL,
                                     uint32_t bh0, uint32_t bh1,
                                     uint32_t bl0, uint32_t bl1) {
    uint32_t b[2];
    b[0] = bh0; b[1] = bh1; mma16816(c, aH, b);
    b[0] = bl0; b[1] = bl1; mma16816(c, aH, b);
    b[0] = bh0; b[1] = bh1; mma16816(c, aL, b);
}

__device__ __forceinline__ void bsplit(float v, __nv_bfloat16& h, __nv_bfloat16& l) {
    h = __float2bfloat16(v);
    l = __float2bfloat16(v - __bfloat162float(h));
}
__device__ __forceinline__ uint32_t pack2(__nv_bfloat16 a, __nv_bfloat16 b) {
    __nv_bfloat162 p(a, b);
    return *reinterpret_cast<uint32_t*>(&p);
}

// ---------------------------------------------------------------------------
// K0: weight prep — W[k][n] -> Wt_h/Wt_l[n][k] bf16. One block per matrix.
// ---------------------------------------------------------------------------
__global__ void prep_weights(const float* w0, const float* w1, const float* w2,
                             const float* w3, const float* w4, const float* w5)
{
    const float* srcs[6] = {w0, w1, w2, w3, w4, w5};
    const float* src = srcs[blockIdx.x];
    const int base = blockIdx.x * DCH * DCH;
    for (int idx = threadIdx.x; idx < DCH * DCH; idx += blockDim.x) {
        int k = idx >> 7, n = idx & 127;
        __nv_bfloat16 h, l;
        bsplit(src[idx], h, l);
        g_Wth[base + n * DCH + k] = h;
        g_Wtl[base + n * DCH + k] = l;
    }
}

// ---------------------------------------------------------------------------
// K1: LayerNorm over D=128 -> Xh/Xl bf16 [pos][d].
// ---------------------------------------------------------------------------
__global__ void ln_split_kernel(const float* __restrict__ pair,
                                const float* __restrict__ lng,
                                const float* __restrict__ lnb)
{
    const int lane = threadIdx.x & 31;
    const int row  = blockIdx.x * 8 + (threadIdx.x >> 5);
    const float4 v = reinterpret_cast<const float4*>(pair)[(size_t)row * 32 + lane];
    float s = v.x + v.y + v.z + v.w;
    float q = v.x*v.x + v.y*v.y + v.z*v.z + v.w*v.w;
#pragma unroll
    for (int o = 16; o > 0; o >>= 1) {
        s += __shfl_xor_sync(0xffffffffu, s, o);
        q += __shfl_xor_sync(0xffffffffu, q, o);
    }
    const float mean = s * (1.0f / 128.0f);
    const float var  = q * (1.0f / 128.0f) - mean * mean;
    const float rs   = rsqrtf(var + 1e-5f);
    const float4 g4 = reinterpret_cast<const float4*>(lng)[lane];
    const float4 b4 = reinterpret_cast<const float4*>(lnb)[lane];
    float o0 = (v.x - mean) * rs * g4.x + b4.x;
    float o1 = (v.y - mean) * rs * g4.y + b4.y;
    float o2 = (v.z - mean) * rs * g4.z + b4.z;
    float o3 = (v.w - mean) * rs * g4.w + b4.w;
    __nv_bfloat16 h0,l0,h1,l1,h2,l2,h3,l3;
    bsplit(o0,h0,l0); bsplit(o1,h1,l1); bsplit(o2,h2,l2); bsplit(o3,h3,l3);
    uint2 hv = make_uint2(pack2(h0,h1), pack2(h2,h3));
    uint2 lv = make_uint2(pack2(l0,l1), pack2(l2,l3));
    *reinterpret_cast<uint2*>(&g_Xh[(size_t)row * DCH + lane * 4]) = hv;
    *reinterpret_cast<uint2*>(&g_Xl[(size_t)row * DCH + lane * 4]) = lv;
}

// ---------------------------------------------------------------------------
// Persistent projection kernels. Weights fully resident in smem (272B rows,
// conflict-free for ldmatrix), A streamed in a 2-buffer cp.async ring with
// uniform group commits. 512 threads = 16 warps = 4M x 4N; warp = 32m x 32n
// per output matrix; M tile = 128 rows; K=128 in 4 stages of 32.
// ---------------------------------------------------------------------------
#define W_RS    272
#define W_MAT   (128 * W_RS)              // 34816
#define A_BUF   (2 * 128 * 80)            // 20480 (hi+lo)
#define NTILES  2048

#define PD_W_SZ  (4 * W_MAT)              // 139264
#define PD_A_OFF PD_W_SZ
#define PD_SCR   (PD_A_OFF + 2 * A_BUF)   // 180224
#define PD_SMEM  (PD_SCR + 64 * 129 * 4)  // 213248

#define PS_W_SZ  (2 * W_MAT)              // 69632
#define PS_A_OFF PS_W_SZ
#define PS_SMEM  (PS_A_OFF + 2 * A_BUF)   // 110592

// dual: v = (X@Wp + bp) * sigmoid(X@Wg + bg) * mask, hi/lo split + transpose
// DST 0 -> g_Lh/g_Ll [d][i][j] (tile = 128 consecutive pos)
// DST 1 -> g_Rh/g_Rl [d][k][j] (tile = fixed k, 128 consecutive j)
template<int WP, int WG, int DST>
__global__ __launch_bounds__(512, 1) void pdual_mma(
    const float* __restrict__ bp, const float* __restrict__ bg,
    const float* __restrict__ mask)
{
    extern __shared__ char smem[];
    const uint32_t sb = (uint32_t)__cvta_generic_to_shared(smem);
    const int t = threadIdx.x, lane = t & 31, wid = t >> 5;
    const int wm = wid & 3, wn = wid >> 2;

    const int myN = (NTILES - (int)blockIdx.x + (int)gridDim.x - 1) / (int)gridDim.x;
    auto tileOf = [&](int i) { return (int)blockIdx.x + i * (int)gridDim.x; };
    auto posOf = [&](int T, int row) -> size_t {
        if (DST == 0) return (size_t)T * 128 + row;
        return (size_t)((T & 3) * 128 + row) * NRES + (T >> 2);
    };

    // Resident weight fill (one shot; part of first commit group)
    {
        const __nv_bfloat16* wsrc[4] = {
            g_Wth + WP * (DCH*DCH), g_Wtl + WP * (DCH*DCH),
            g_Wth + WG * (DCH*DCH), g_Wtl + WG * (DCH*DCH) };
#pragma unroll
        for (int q = 0; q < 16; q++) {
            int idx = t + q * 512;
            int m = idx >> 11, r = (idx >> 4) & 127, c = idx & 15;
            cp16(smem + m * W_MAT + r * W_RS + c * 16, wsrc[m] + r * DCH + c * 8);
        }
    }

    auto fillA = [&](int g) {
        int ti = g >> 2, s = g & 3;
        if (ti >= myN) return;
        int T = tileOf(ti);
        char* base = smem + PD_A_OFF + (g & 1) * A_BUF;
#pragma unroll
        for (int q = 0; q < 2; q++) {
            int c = t + q * 512;
            int hl = c >> 9, row = (c >> 2) & 127, col = c & 3;
            const __nv_bfloat16* src = hl ? g_Xl : g_Xh;
            cp16(base + hl * 10240 + row * 80 + col * 16,
                 src + posOf(T, row) * DCH + s * 32 + col * 8);
        }
    };

    fillA(0); asm volatile("cp.async.commit_group;");
    fillA(1); asm volatile("cp.async.commit_group;");

    const uint32_t aLane = (uint32_t)((lane & 15) * 80  + ((lane >> 4) << 4));
    const uint32_t bLane = (uint32_t)((lane & 15) * W_RS + ((lane >> 4) << 4));

    for (int i = 0; i < myN; i++) {
        const int T = tileOf(i);
        float accP[2][4][4], accG[2][4][4];
#pragma unroll
        for (int mt = 0; mt < 2; mt++)
#pragma unroll
            for (int nt = 0; nt < 4; nt++)
#pragma unroll
                for (int c = 0; c < 4; c++) { accP[mt][nt][c] = 0.f; accG[mt][nt][c] = 0.f; }

        for (int s = 0; s < 4; s++) {
            const int g = i * 4 + s;
            asm volatile("cp.async.wait_group 1;");
            __syncthreads();
            const uint32_t ab  = sb + PD_A_OFF + (g & 1) * A_BUF;
            const uint32_t wko = (uint32_t)(s * 64);
#pragma unroll
            for (int kh = 0; kh < 2; kh++) {
                uint32_t aH[2][4], aL[2][4];
#pragma unroll
                for (int mt = 0; mt < 2; mt++) {
                    ldsm_x4(aH[mt], ab + (wm*32 + mt*16) * 80 + aLane + kh*32);
                    ldsm_x4(aL[mt], ab + 10240 + (wm*32 + mt*16) * 80 + aLane + kh*32);
                }
#pragma unroll
                for (int ntp = 0; ntp < 2; ntp++) {
                    const uint32_t nb = (uint32_t)((wn*32 + ntp*16) * W_RS) + bLane + wko + kh*32;
                    uint32_t pH[4], pL[4], gH[4], gL[4];
                    ldsm_x4(pH, sb + nb);
                    ldsm_x4(pL, sb + W_MAT + nb);
                    ldsm_x4(gH, sb + 2*W_MAT + nb);
                    ldsm_x4(gL, sb + 3*W_MAT + nb);
#pragma unroll
                    for (int mt = 0; mt < 2; mt++) {
                        mma3(accP[mt][2*ntp  ], aH[mt], aL[mt], pH[0], pH[2], pL[0], pL[2]);
                        mma3(accP[mt][2*ntp+1], aH[mt], aL[mt], pH[1], pH[3], pL[1], pL[3]);
                        mma3(accG[mt][2*ntp  ], aH[mt], aL[mt], gH[0], gH[2], gL[0], gL[2]);
                        mma3(accG[mt][2*ntp+1], aH[mt], aL[mt], gH[1], gH[3], gL[1], gL[3]);
                    }
                }
            }
            __syncthreads();
            fillA(g + 2);
            asm volatile("cp.async.commit_group;");
        }

        // Epilogue: two 64-row passes through fp32 scratch, bsplit, d-major
        float* sP = reinterpret_cast<float*>(smem + PD_SCR);
        const int gq = lane >> 2, kc = (lane & 3) * 2;
#pragma unroll
        for (int pass = 0; pass < 2; pass++) {
            if ((wm >> 1) == pass) {
                const int mbase = (wm & 1) * 32;
#pragma unroll
                for (int mt = 0; mt < 2; mt++) {
                    const int rloc = mbase + mt * 16 + gq;
                    const float mA = mask[posOf(T, pass * 64 + rloc)];
                    const float mB = mask[posOf(T, pass * 64 + rloc + 8)];
#pragma unroll
                    for (int nt = 0; nt < 4; nt++) {
                        const int col = wn * 32 + nt * 8 + kc;
                        const float bp0 = bp[col], bp1 = bp[col + 1];
                        const float bg0 = bg[col], bg1 = bg[col + 1];
                        sP[rloc*129 + col    ] = (accP[mt][nt][0]+bp0)*fsig(accG[mt][nt][0]+bg0)*mA;
                        sP[rloc*129 + col + 1] = (accP[mt][nt][1]+bp1)*fsig(accG[mt][nt][1]+bg1)*mA;
                        sP[(rloc+8)*129 + col    ] = (accP[mt][nt][2]+bp0)*fsig(accG[mt][nt][2]+bg0)*mB;
                        sP[(rloc+8)*129 + col + 1] = (accP[mt][nt][3]+bp1)*fsig(accG[mt][nt][3]+bg1)*mB;
                    }
                }
            }
            __syncthreads();
            {
                const int dch = t >> 2, sub = t & 3;
                uint32_t wh[8], wl[8];
#pragma unroll
                for (int q = 0; q < 8; q++) {
                    __nv_bfloat16 h0, l0, h1, l1;
                    bsplit(sP[(sub*16 + 2*q    ) * 129 + dch], h0, l0);
                    bsplit(sP[(sub*16 + 2*q + 1) * 129 + dch], h1, l1);
                    wh[q] = pack2(h0, h1);
                    wl[q] = pack2(l0, l1);
                }
                size_t plane;
                if (DST == 0) plane = (size_t)T * 128;
                else          plane = (size_t)(T >> 2) * NRES + (T & 3) * 128;
                const size_t ob = (size_t)dch * NPOS + plane + pass * 64 + sub * 16;
                __nv_bfloat16* __restrict__ dH = DST ? g_Rh : g_Lh;
                __nv_bfloat16* __restrict__ dL = DST ? g_Rl : g_Ll;
                *reinterpret_cast<uint4*>(&dH[ob])     = make_uint4(wh[0], wh[1], wh[2], wh[3]);
                *reinterpret_cast<uint4*>(&dH[ob + 8]) = make_uint4(wh[4], wh[5], wh[6], wh[7]);
                *reinterpret_cast<uint4*>(&dL[ob])     = make_uint4(wl[0], wl[1], wl[2], wl[3]);
                *reinterpret_cast<uint4*>(&dL[ob + 8]) = make_uint4(wl[4], wl[5], wl[6], wl[7]);
            }
            __syncthreads();
        }
    }
}

// single: EPI 1: g_gate = sigmoid(X@W + b);  EPI 0: dstExt = PRE@W + b
template<int WIDX, int EPI>
__global__ __launch_bounds__(512, 2) void psingle_mma(
    const float* __restrict__ bias, float* __restrict__ dstExt)
{
    extern __shared__ char smem[];
    const uint32_t sb = (uint32_t)__cvta_generic_to_shared(smem);
    const int t = threadIdx.x, lane = t & 31, wid = t >> 5;
    const int wm = wid & 3, wn = wid >> 2;
    const __nv_bfloat16* __restrict__ ah = (EPI == 1) ? g_Xh : g_Lh;
    const __nv_bfloat16* __restrict__ al = (EPI == 1) ? g_Xl : g_Ll;
    float* __restrict__ dst = (EPI == 1) ? g_gate : dstExt;

    const int myN = (NTILES - (int)blockIdx.x + (int)gridDim.x - 1) / (int)gridDim.x;
    auto tileOf = [&](int i) { return (int)blockIdx.x + i * (int)gridDim.x; };

    {
        const __nv_bfloat16* wsrc[2] = { g_Wth + WIDX * (DCH*DCH), g_Wtl + WIDX * (DCH*DCH) };
#pragma unroll
        for (int q = 0; q < 8; q++) {
            int idx = t + q * 512;
            int m = idx >> 11, r = (idx >> 4) & 127, c = idx & 15;
            cp16(smem + m * W_MAT + r * W_RS + c * 16, wsrc[m] + r * DCH + c * 8);
        }
    }

    auto fillA = [&](int g) {
        int ti = g >> 2, s = g & 3;
        if (ti >= myN) return;
        size_t rowbase = (size_t)tileOf(ti) * 128;
        char* base = smem + PS_A_OFF + (g & 1) * A_BUF;
#pragma unroll
        for (int q = 0; q < 2; q++) {
            int c = t + q * 512;
            int hl = c >> 9, row = (c >> 2) & 127, col = c & 3;
            const __nv_bfloat16* src = hl ? al : ah;
            cp16(base + hl * 10240 + row * 80 + col * 16,
                 src + (rowbase + row) * DCH + s * 32 + col * 8);
        }
    };

    fillA(0); asm volatile("cp.async.commit_group;");
    fillA(1); asm volatile("cp.async.commit_group;");

    const uint32_t aLane = (uint32_t)((lane & 15) * 80  + ((lane >> 4) << 4));
    const uint32_t bLane = (uint32_t)((lane & 15) * W_RS + ((lane >> 4) << 4));

    for (int i = 0; i < myN; i++) {
        const int T = tileOf(i);
        float acc[2][4][4];
#pragma unroll
        for (int mt = 0; mt < 2; mt++)
#pragma unroll
            for (int nt = 0; nt < 4; nt++)
#pragma unroll
                for (int c = 0; c < 4; c++) acc[mt][nt][c] = 0.f;

        for (int s = 0; s < 4; s++) {
            const int g = i * 4 + s;
            asm volatile("cp.async.wait_group 1;");
            __syncthreads();
            const uint32_t ab  = sb + PS_A_OFF + (g & 1) * A_BUF;
            const uint32_t wko = (uint32_t)(s * 64);
#pragma unroll
            for (int kh = 0; kh < 2; kh++) {
                uint32_t aH[2][4], aL[2][4];
#pragma unroll
                for (int mt = 0; mt < 2; mt++) {
                    ldsm_x4(aH[mt], ab + (wm*32 + mt*16) * 80 + aLane + kh*32);
                    ldsm_x4(aL[mt], ab + 10240 + (wm*32 + mt*16) * 80 + aLane + kh*32);
                }
#pragma unroll
                for (int ntp = 0; ntp < 2; ntp++) {
                    const uint32_t nb = (uint32_t)((wn*32 + ntp*16) * W_RS) + bLane + wko + kh*32;
                    uint32_t bH[4], bL[4];
                    ldsm_x4(bH, sb + nb);
                    ldsm_x4(bL, sb + W_MAT + nb);
#pragma unroll
                    for (int mt = 0; mt < 2; mt++) {
                        mma3(acc[mt][2*ntp  ], aH[mt], aL[mt], bH[0], bH[2], bL[0], bL[2]);
                        mma3(acc[mt][2*ntp+1], aH[mt], aL[mt], bH[1], bH[3], bL[1], bL[3]);
                    }
                }
            }
            __syncthreads();
            fillA(g + 2);
            asm volatile("cp.async.commit_group;");
        }

        const int gq = lane >> 2, kc = (lane & 3) * 2;
#pragma unroll
        for (int mt = 0; mt < 2; mt++) {
            const size_t ra = (size_t)T * 128 + wm * 32 + mt * 16 + gq;
#pragma unroll
            for (int nt = 0; nt < 4; nt++) {
                const int col = wn * 32 + nt * 8 + kc;
                const float b0 = bias[col], b1 = bias[col + 1];
                float2 oa, ob;
                oa.x = acc[mt][nt][0] + b0; oa.y = acc[mt][nt][1] + b1;
                ob.x = acc[mt][nt][2] + b0; ob.y = acc[mt][nt][3] + b1;
                if (EPI == 1) { oa.x = fsig(oa.x); oa.y = fsig(oa.y);
                                ob.x = fsig(ob.x); ob.y = fsig(ob.y); }
                *reinterpret_cast<float2*>(&dst[ra * DCH + col]) = oa;
                *reinterpret_cast<float2*>(&dst[(ra + 8) * DCH + col]) = ob;
            }
        }
    }
}

// ---------------------------------------------------------------------------
// K4: einsum via mma.sync (R8/R9, proven — unchanged).
// ---------------------------------------------------------------------------
#define EM_RS     80
#define EM_A_T    (128 * EM_RS)
#define EM_B_T    (64 * EM_RS)
#define EM_STAGE  (2 * EM_A_T + 2 * EM_B_T)
#define EM_SMEM   (3 * EM_STAGE)

__global__ __launch_bounds__(256, 2) void einsum_mma_kernel()
{
    extern __shared__ char smem[];
    const uint32_t sbase = (uint32_t)__cvta_generic_to_shared(smem);
    const int t    = threadIdx.x;
    const int lane = t & 31;
    const int wid  = t >> 5;
    const int wm   = wid & 3;
    const int wn   = wid >> 2;

    const int bid = blockIdx.x;
    const int d   = bid >> 5;
    const int i0  = ((bid >> 3) & 3) * 128;
    const int k0  = (bid & 7) * 64;

    const __nv_bfloat16* __restrict__ pLh = g_Lh + (size_t)d * NPOS + (size_t)i0 * NRES;
    const __nv_bfloat16* __restrict__ pLl = g_Ll + (size_t)d * NPOS + (size_t)i0 * NRES;
    const __nv_bfloat16* __restrict__ pRh = g_Rh + (size_t)d * NPOS + (size_t)k0 * NRES;
    const __nv_bfloat16* __restrict__ pRl = g_Rl + (size_t)d * NPOS + (size_t)k0 * NRES;

    float acc[2][4][4];
#pragma unroll
    for (int mt = 0; mt < 2; mt++)
#pragma unroll
        for (int nt = 0; nt < 4; nt++)
#pragma unroll
            for (int c = 0; c < 4; c++) acc[mt][nt][c] = 0.0f;

    auto fill = [&](int s) {
        const int buf = s % 3;
        char* base = smem + buf * EM_STAGE;
        const int j0s = s * 32;
        {
            int c0 = t, c1 = t + 256;
            int r0 = c0 >> 2, r1 = c1 >> 2, col0 = c0 & 3, col1 = c1 & 3;
            cp16(base + r0 * EM_RS + col0 * 16,
                 pLh + (size_t)r0 * NRES + j0s + col0 * 8);
            cp16(base + r1 * EM_RS + col1 * 16,
                 pLh + (size_t)r1 * NRES + j0s + col1 * 8);
            cp16(base + EM_A_T + r0 * EM_RS + col0 * 16,
                 pLl + (size_t)r0 * NRES + j0s + col0 * 8);
            cp16(base + EM_A_T + r1 * EM_RS + col1 * 16,
                 pLl + (size_t)r1 * NRES + j0s + col1 * 8);
        }
        {
            int r = t >> 2, col = t & 3;
            cp16(base + 2 * EM_A_T + r * EM_RS + col * 16,
                 pRh + (size_t)r * NRES + j0s + col * 8);
            cp16(base + 2 * EM_A_T + EM_B_T + r * EM_RS + col * 16,
                 pRl + (size_t)r * NRES + j0s + col * 8);
        }
    };

    fill(0); asm volatile("cp.async.commit_group;");
    fill(1); asm volatile("cp.async.commit_group;");

    const uint32_t aOff = (uint32_t)((wm * 32 + ((lane >> 3) & 1) * 8 + (lane & 7)) * EM_RS
                                     + ((lane >> 4) << 4));
    const uint32_t bOff = (uint32_t)((wn * 32 + (lane & 7)) * EM_RS
                                     + (((lane >> 3) & 1) << 4));

    for (int s = 0; s < 16; s++) {
        asm volatile("cp.async.wait_group 1;");
        __syncthreads();
        if (s + 2 < 16) fill(s + 2);
        asm volatile("cp.async.commit_group;");

        const uint32_t sb  = sbase + (s % 3) * EM_STAGE;
        const uint32_t aHb = sb, aLb = sb + EM_A_T;
        const uint32_t bHb = sb + 2 * EM_A_T, bLb = bHb + EM_B_T;

#pragma unroll
        for (int kh = 0; kh < 2; kh++) {
            const uint32_t kb = kh * 32;
            uint32_t aH[2][4], aL[2][4];
            ldsm_x4(aH[0], aHb + aOff + kb);
            ldsm_x4(aH[1], aHb + aOff + 16 * EM_RS + kb);
            ldsm_x4(aL[0], aLb + aOff + kb);
            ldsm_x4(aL[1], aLb + aOff + 16 * EM_RS + kb);
#pragma unroll
            for (int nt = 0; nt < 4; nt++) {
                uint32_t bH[2], bL[2];
                ldsm_x2(bH, bHb + bOff + nt * 8 * EM_RS + kb);
                ldsm_x2(bL, bLb + bOff + nt * 8 * EM_RS + kb);
#pragma unroll
                for (int mt = 0; mt < 2; mt++) {
                    mma16816(acc[mt][nt], aH[mt], bH);
                    mma16816(acc[mt][nt], aH[mt], bL);
                    mma16816(acc[mt][nt], aL[mt], bH);
                }
            }
        }
    }

    float* __restrict__ pOut = g_pret + (size_t)d * NPOS;
    const int g  = lane >> 2;
    const int kc = (lane & 3) * 2;
#pragma unroll
    for (int mt = 0; mt < 2; mt++) {
#pragma unroll
        for (int nt = 0; nt < 4; nt++) {
            const int i = i0 + wm * 32 + mt * 16 + g;
            const int k = k0 + wn * 32 + nt * 8 + kc;
            *reinterpret_cast<float2*>(&pOut[(size_t)i * NRES + k]) =
                make_float2(acc[mt][nt][0], acc[mt][nt][1]);
            *reinterpret_cast<float2*>(&pOut[(size_t)(i + 8) * NRES + k]) =
                make_float2(acc[mt][nt][2], acc[mt][nt][3]);
        }
    }
}

// ---------------------------------------------------------------------------
// T3: pre = pret^T * gate -> split into Ph/Pl bf16 [pos][d] (reuses g_Lh/g_Ll)
// ---------------------------------------------------------------------------
__global__ __launch_bounds__(256) void fuse_gate_kernel()
{
    __shared__ float sP[32][128];
    const int t = threadIdx.x;
    const size_t pos0 = (size_t)blockIdx.x * 32;
    const int d = t >> 1, h = (t & 1) * 16;
#pragma unroll
    for (int q = 0; q < 4; q++) {
        float4 v = reinterpret_cast<const float4*>(g_pret)[
            ((size_t)d * NPOS + pos0 + h) / 4 + q];
        sP[h + q*4 + 0][d] = v.x;
        sP[h + q*4 + 1][d] = v.y;
        sP[h + q*4 + 2][d] = v.z;
        sP[h + q*4 + 3][d] = v.w;
    }
    __syncthreads();
#pragma unroll
    for (int q = 0; q < 4; q++) {
        int idx = t + q * 256;
        int row = idx >> 5, c4 = idx & 31;
        float4 p = *reinterpret_cast<float4*>(&sP[row][c4 * 4]);
        float4 g = reinterpret_cast<const float4*>(g_gate)[(pos0 + row) * 32 + c4];
        p.x *= g.x; p.y *= g.y; p.z *= g.z; p.w *= g.w;
        __nv_bfloat16 h0,l0,h1,l1,h2,l2,h3,l3;
        bsplit(p.x,h0,l0); bsplit(p.y,h1,l1); bsplit(p.z,h2,l2); bsplit(p.w,h3,l3);
        const size_t o = (pos0 + row) * DCH + c4 * 4;
        *reinterpret_cast<uint2*>(&g_Lh[o]) = make_uint2(pack2(h0,h1), pack2(h2,h3));
        *reinterpret_cast<uint2*>(&g_Ll[o]) = make_uint2(pack2(l0,l1), pack2(l2,l3));
    }
}

// ---------------------------------------------------------------------------
extern "C" void kernel_launch(void* const* d_in, const int* in_sizes, int n_in,
                              void* d_out, int out_size)
{
    (void)in_sizes; (void)n_in; (void)out_size;
    const float* pair = (const float*)d_in[0];
    const float* mask = (const float*)d_in[1];
    const float* ln_g = (const float*)d_in[2];
    const float* ln_b = (const float*)d_in[3];
    const float* w_lp = (const float*)d_in[4];
    const float* b_lp = (const float*)d_in[5];
    const float* w_lg = (const float*)d_in[6];
    const float* b_lg = (const float*)d_in[7];
    const float* w_rp = (const float*)d_in[8];
    const float* b_rp = (const float*)d_in[9];
    const float* w_rg = (const float*)d_in[10];
    const float* b_rg = (const float*)d_in[11];
    const float* w_g  = (const float*)d_in[12];
    const float* b_g  = (const float*)d_in[13];
    const float* w_o  = (const float*)d_in[14];
    const float* b_o  = (const float*)d_in[15];
    float* out = (float*)d_out;

    cudaFuncSetAttribute(einsum_mma_kernel,
                         cudaFuncAttributeMaxDynamicSharedMemorySize, EM_SMEM);
    cudaFuncSetAttribute(pdual_mma<0,1,0>,
                         cudaFuncAttributeMaxDynamicSharedMemorySize, PD_SMEM);
    cudaFuncSetAttribute(pdual_mma<2,3,1>,
                         cudaFuncAttributeMaxDynamicSharedMemorySize, PD_SMEM);
    cudaFuncSetAttribute(psingle_mma<4,1>,
                         cudaFuncAttributeMaxDynamicSharedMemorySize, PS_SMEM);
    cudaFuncSetAttribute(psingle_mma<5,0>,
                         cudaFuncAttributeMaxDynamicSharedMemorySize, PS_SMEM);

    prep_weights<<<6, 256>>>(w_lp, w_lg, w_rp, w_rg, w_g, w_o);
    ln_split_kernel<<<NPOS / 8, 256>>>(pair, ln_g, ln_b);
    pdual_mma<0,1,0><<<152, 512, PD_SMEM>>>(b_lp, b_lg, mask);
    pdual_mma<2,3,1><<<152, 512, PD_SMEM>>>(b_rp, b_rg, mask);
    psingle_mma<4,1><<<304, 512, PS_SMEM>>>(b_g, nullptr);
    einsum_mma_kernel<<<4096, 256, EM_SMEM>>>();
    fuse_gate_kernel<<<NPOS / 32, 256>>>();
    psingle_mma<5,0><<<304, 512, PS_SMEM>>>(b_o, out);
}

// round 12
// speedup vs baseline: 1.0229x; 1.0229x over previous
#include <cuda_runtime.h>
#include <cuda_bf16.h>
#include <cstdint>

#define NRES 512
#define DCH  128
#define NPOS (NRES*NRES)

// Scratch (device globals — no runtime allocation allowed)
__device__ float g_gate [(size_t)NPOS * DCH];
__device__ float g_pret [(size_t)NPOS * DCH];        // [d][i][k]
__device__ __nv_bfloat16 g_Xh[(size_t)NPOS * DCH];   // LN(x) split, [pos][d]
__device__ __nv_bfloat16 g_Xl[(size_t)NPOS * DCH];
__device__ __nv_bfloat16 g_Lh[(size_t)DCH * NPOS];   // [d][i][j]; later pre-split [pos][d]
__device__ __nv_bfloat16 g_Ll[(size_t)DCH * NPOS];
__device__ __nv_bfloat16 g_Rh[(size_t)DCH * NPOS];   // [d][k][j]
__device__ __nv_bfloat16 g_Rl[(size_t)DCH * NPOS];
__device__ __nv_bfloat16 g_Wth[6 * DCH * DCH];       // W^T hi, [widx][n][k]
__device__ __nv_bfloat16 g_Wtl[6 * DCH * DCH];       // W^T lo

__device__ __forceinline__ float fsig(float x) { return 1.0f / (1.0f + __expf(-x)); }

__device__ __forceinline__ void cp16(void* s, const void* g) {
    unsigned sa = (unsigned)__cvta_generic_to_shared(s);
    asm volatile("cp.async.cg.shared.global [%0], [%1], 16;" :: "r"(sa), "l"(g));
}

// ---- mma.sync / ldmatrix (sm_80-class PTX: compiles on plain sm_103) ------
__device__ __forceinline__ void ldsm_x4(uint32_t* r, uint32_t addr) {
    asm volatile("ldmatrix.sync.aligned.m8n8.x4.shared.b16 {%0,%1,%2,%3}, [%4];"
        : "=r"(r[0]), "=r"(r[1]), "=r"(r[2]), "=r"(r[3]) : "r"(addr));
}
__device__ __forceinline__ void mma16816(float* c, const uint32_t* a, const uint32_t* b) {
    asm volatile("mma.sync.aligned.m16n8k16.row.col.f32.bf16.bf16.f32 "
        "{%0,%1,%2,%3}, {%4,%5,%6,%7}, {%8,%9}, {%0,%1,%2,%3};"
        : "+f"(c[0]), "+f"(c[1]), "+f"(c[2]), "+f"(c[3])
        : "r"(a[0]), "r"(a[1]), "r"(a[2]), "r"(a[3]), "r"(b[0]), "r"(b[1]));
}
// C += Ah*Bh + Ah*Bl + Al*Bh   (bf16 hi/lo split product)
__device__ __forceinline__ void mma3(float* c, const uint32_t* aH, const uint32_t* aL,
                                     uint32_t bh0, uint32_t bh1,
                                     uint32_t bl0, uint32_t bl1) {
    uint32_t b[2];
    b[0] = bh0; b[1] = bh1; mma16816(c, aH, b);
    b[0] = bl0; b[1] = bl1; mma16816(c, aH, b);
    b[0] = bh0; b[1] = bh1; mma16816(c, aL, b);
}

__device__ __forceinline__ void bsplit(float v, __nv_bfloat16& h, __nv_bfloat16& l) {
    h = __float2bfloat16(v);
    l = __float2bfloat16(v - __bfloat162float(h));
}
__device__ __forceinline__ uint32_t pack2(__nv_bfloat16 a, __nv_bfloat16 b) {
    __nv_bfloat162 p(a, b);
    return *reinterpret_cast<uint32_t*>(&p);
}

// ---------------------------------------------------------------------------
// K0: weight prep — W[k][n] -> Wt_h/Wt_l[n][k] bf16. One block per matrix.
// ---------------------------------------------------------------------------
__global__ void prep_weights(const float* w0, const float* w1, const float* w2,
                             const float* w3, const float* w4, const float* w5)
{
    const float* srcs[6] = {w0, w1, w2, w3, w4, w5};
    const float* src = srcs[blockIdx.x];
    const int base = blockIdx.x * DCH * DCH;
    for (int idx = threadIdx.x; idx < DCH * DCH; idx += blockDim.x) {
        int k = idx >> 7, n = idx & 127;
        __nv_bfloat16 h, l;
        bsplit(src[idx], h, l);
        g_Wth[base + n * DCH + k] = h;
        g_Wtl[base + n * DCH + k] = l;
    }
}

// ---------------------------------------------------------------------------
// K1: LayerNorm over D=128 -> Xh/Xl bf16 [pos][d].
// ---------------------------------------------------------------------------
__global__ void ln_split_kernel(const float* __restrict__ pair,
                                const float* __restrict__ lng,
                                const float* __restrict__ lnb)
{
    const int lane = threadIdx.x & 31;
    const int row  = blockIdx.x * 8 + (threadIdx.x >> 5);
    const float4 v = reinterpret_cast<const float4*>(pair)[(size_t)row * 32 + lane];
    float s = v.x + v.y + v.z + v.w;
    float q = v.x*v.x + v.y*v.y + v.z*v.z + v.w*v.w;
#pragma unroll
    for (int o = 16; o > 0; o >>= 1) {
        s += __shfl_xor_sync(0xffffffffu, s, o);
        q += __shfl_xor_sync(0xffffffffu, q, o);
    }
    const float mean = s * (1.0f / 128.0f);
    const float var  = q * (1.0f / 128.0f) - mean * mean;
    const float rs   = rsqrtf(var + 1e-5f);
    const float4 g4 = reinterpret_cast<const float4*>(lng)[lane];
    const float4 b4 = reinterpret_cast<const float4*>(lnb)[lane];
    float o0 = (v.x - mean) * rs * g4.x + b4.x;
    float o1 = (v.y - mean) * rs * g4.y + b4.y;
    float o2 = (v.z - mean) * rs * g4.z + b4.z;
    float o3 = (v.w - mean) * rs * g4.w + b4.w;
    __nv_bfloat16 h0,l0,h1,l1,h2,l2,h3,l3;
    bsplit(o0,h0,l0); bsplit(o1,h1,l1); bsplit(o2,h2,l2); bsplit(o3,h3,l3);
    uint2 hv = make_uint2(pack2(h0,h1), pack2(h2,h3));
    uint2 lv = make_uint2(pack2(l0,l1), pack2(l2,l3));
    *reinterpret_cast<uint2*>(&g_Xh[(size_t)row * DCH + lane * 4]) = hv;
    *reinterpret_cast<uint2*>(&g_Xl[(size_t)row * DCH + lane * 4]) = lv;
}

// ---------------------------------------------------------------------------
// Projection GEMMs on mma.sync. M tile 64 x N 128, K=128 in 4 stages of 32.
// 8 warps = 4M x 2N, warp = 16 rows x 64 cols.
// ---------------------------------------------------------------------------
#define PJ_RS      80
#define PJ_A_T     (64 * PJ_RS)               // 5120
#define PJ_B_T     (128 * PJ_RS)              // 10240
#define PJ_STAGE_D (2*PJ_A_T + 4*PJ_B_T)      // 51200
#define PJ_SMEM_D  (2 * PJ_STAGE_D)           // 102400
#define PJ_STAGE_S (2*PJ_A_T + 2*PJ_B_T)      // 30720
#define PJ_SMEM_S  (2 * PJ_STAGE_S)           // 61440

// dual: v = (X@Wp + bp) * sigmoid(X@Wg + bg) * mask, then hi/lo split + transpose
// DST 0 -> g_Lh/g_Ll [d][i][j] (rows = 64 consecutive pos, fixed i)
// DST 1 -> g_Rh/g_Rl [d][k][j] (rows = pos (j0+r)*512+kk, fixed k; kk is the
//          FAST block index so concurrent CTAs read adjacent X segments)
template<int WP, int WG, int DST>
__global__ __launch_bounds__(256, 2) void proj_dual_mma(
    const float* __restrict__ bp, const float* __restrict__ bg,
    const float* __restrict__ mask)
{
    extern __shared__ char smem[];
    const uint32_t sbase = (uint32_t)__cvta_generic_to_shared(smem);
    const int t = threadIdx.x, lane = t & 31, wid = t >> 5;
    const int wm = wid & 3, wn = wid >> 2;

    // row mapping
    const int row0 = blockIdx.x * 64;          // DST==0
    const int kk   = blockIdx.x & 511;         // DST==1 (fast index: locality)
    const int j0   = (blockIdx.x >> 9) * 64;   // DST==1

    auto apos = [&](int row) -> size_t {
        if (DST == 0) return (size_t)(row0 + row);
        else          return (size_t)(j0 + row) * NRES + kk;
    };

    const __nv_bfloat16* __restrict__ wph = g_Wth + WP * (DCH*DCH);
    const __nv_bfloat16* __restrict__ wpl = g_Wtl + WP * (DCH*DCH);
    const __nv_bfloat16* __restrict__ wgh = g_Wth + WG * (DCH*DCH);
    const __nv_bfloat16* __restrict__ wgl = g_Wtl + WG * (DCH*DCH);

    float accP[8][4], accG[8][4];
#pragma unroll
    for (int nt = 0; nt < 8; nt++)
#pragma unroll
        for (int c = 0; c < 4; c++) { accP[nt][c] = 0.f; accG[nt][c] = 0.f; }

    auto fill = [&](int s) {
        char* base = smem + (s & 1) * PJ_STAGE_D;
#pragma unroll
        for (int q = 0; q < 2; q++) {           // A: Xh, Xl
            int c = t + q * 256;
            int hl = c >> 8, row = (c >> 2) & 63, col = c & 3;
            const __nv_bfloat16* src = hl ? g_Xl : g_Xh;
            cp16(base + hl * PJ_A_T + row * PJ_RS + col * 16,
                 src + apos(row) * DCH + s * 32 + col * 8);
        }
        const __nv_bfloat16* wsrc[4] = {wph, wpl, wgh, wgl};
#pragma unroll
        for (int q = 0; q < 8; q++) {           // B: ph, pl, gh, gl
            int c = t + q * 256;
            int m = c >> 9, n = (c >> 2) & 127, col = c & 3;
            cp16(base + 2 * PJ_A_T + m * PJ_B_T + n * PJ_RS + col * 16,
                 wsrc[m] + n * DCH + s * 32 + col * 8);
        }
    };

    fill(0); asm volatile("cp.async.commit_group;");
    fill(1); asm volatile("cp.async.commit_group;");

    const uint32_t aOff = (uint32_t)((wm * 16 + (lane & 15)) * PJ_RS + ((lane >> 4) << 4));
    const uint32_t bOff = (uint32_t)((wn * 64 + (lane & 15)) * PJ_RS + ((lane >> 4) << 4));

    for (int s = 0; s < 4; s++) {
        asm volatile("cp.async.wait_group 1;");
        __syncthreads();
        const uint32_t sb = sbase + (s & 1) * PJ_STAGE_D;
#pragma unroll
        for (int kh = 0; kh < 2; kh++) {
            uint32_t aH[4], aL[4];
            ldsm_x4(aH, sb + aOff + kh * 32);
            ldsm_x4(aL, sb + PJ_A_T + aOff + kh * 32);
#pragma unroll
            for (int ntp = 0; ntp < 4; ntp++) {
                const uint32_t bo = bOff + ntp * 16 * PJ_RS + kh * 32;
                uint32_t pH[4], pL[4], gH[4], gL[4];
                ldsm_x4(pH, sb + 2*PJ_A_T + bo);
                ldsm_x4(pL, sb + 2*PJ_A_T + PJ_B_T + bo);
                ldsm_x4(gH, sb + 2*PJ_A_T + 2*PJ_B_T + bo);
                ldsm_x4(gL, sb + 2*PJ_A_T + 3*PJ_B_T + bo);
                mma3(accP[2*ntp  ], aH, aL, pH[0], pH[2], pL[0], pL[2]);
                mma3(accP[2*ntp+1], aH, aL, pH[1], pH[3], pL[1], pL[3]);
                mma3(accG[2*ntp  ], aH, aL, gH[0], gH[2], gL[0], gL[2]);
                mma3(accG[2*ntp+1], aH, aL, gH[1], gH[3], gL[1], gL[3]);
            }
        }
        __syncthreads();                 // all warps done reading buffer s&1
        if (s + 2 < 4) fill(s + 2);
        asm volatile("cp.async.commit_group;");
    }

    // ---- Epilogue: gated value -> smem fp32 [64][129] -> bf16 hi/lo, d-major
    float* sP = reinterpret_cast<float*>(smem);   // 64*129*4 = 33024 B, fits
    const int g  = lane >> 2;
    const int kc = (lane & 3) * 2;
    const int ra = wm * 16 + g, rb = ra + 8;      // tile-local rows
    const float ma = mask[apos(ra)];
    const float mb = mask[apos(rb)];
#pragma unroll
    for (int nt = 0; nt < 8; nt++) {
        const int col = wn * 64 + nt * 8 + kc;
        const float bp0 = bp[col], bp1 = bp[col + 1];
        const float bg0 = bg[col], bg1 = bg[col + 1];
        sP[ra * 129 + col    ] = (accP[nt][0] + bp0) * fsig(accG[nt][0] + bg0) * ma;
        sP[ra * 129 + col + 1] = (accP[nt][1] + bp1) * fsig(accG[nt][1] + bg1) * ma;
        sP[rb * 129 + col    ] = (accP[nt][2] + bp0) * fsig(accG[nt][2] + bg0) * mb;
        sP[rb * 129 + col + 1] = (accP[nt][3] + bp1) * fsig(accG[nt][3] + bg1) * mb;
    }
    __syncthreads();
    // thread t: channel dch = t>>1, rows h..h+31 (h = 0 or 32)
    const int dch = t >> 1, h = (t & 1) * 32;
    uint32_t wh[16], wl[16];
#pragma unroll
    for (int q = 0; q < 16; q++) {
        __nv_bfloat16 h0, l0, h1, l1;
        bsplit(sP[(h + 2*q    ) * 129 + dch], h0, l0);
        bsplit(sP[(h + 2*q + 1) * 129 + dch], h1, l1);
        wh[q] = pack2(h0, h1);
        wl[q] = pack2(l0, l1);
    }
    size_t ob;
    if (DST == 0) ob = (size_t)dch * NPOS + row0 + h;                     // [d][pos]
    else          ob = (size_t)dch * NPOS + (size_t)kk * NRES + j0 + h;   // [d][k][j]
    __nv_bfloat16* __restrict__ dH = DST ? g_Rh : g_Lh;
    __nv_bfloat16* __restrict__ dL = DST ? g_Rl : g_Ll;
#pragma unroll
    for (int q = 0; q < 4; q++) {
        *reinterpret_cast<uint4*>(&dH[ob + q * 8]) =
            make_uint4(wh[q*4], wh[q*4+1], wh[q*4+2], wh[q*4+3]);
        *reinterpret_cast<uint4*>(&dL[ob + q * 8]) =
            make_uint4(wl[q*4], wl[q*4+1], wl[q*4+2], wl[q*4+3]);
    }
}

// single: EPI 1: g_gate = sigmoid(X@W + b);  EPI 0: dstExt = PRE@W + b
// 3 CTAs/SM for deeper HMMA occupancy.
template<int WIDX, int EPI>
__global__ __launch_bounds__(256, 3) void proj_single_mma(
    const float* __restrict__ bias, float* __restrict__ dstExt)
{
    extern __shared__ char smem[];
    const uint32_t sbase = (uint32_t)__cvta_generic_to_shared(smem);
    const int t = threadIdx.x, lane = t & 31, wid = t >> 5;
    const int wm = wid & 3, wn = wid >> 2;
    const int row0 = blockIdx.x * 64;
    const __nv_bfloat16* __restrict__ ah = (EPI == 1) ? g_Xh : g_Lh;
    const __nv_bfloat16* __restrict__ al = (EPI == 1) ? g_Xl : g_Ll;
    float* __restrict__ dst = (EPI == 1) ? g_gate : dstExt;

    const __nv_bfloat16* __restrict__ wh = g_Wth + WIDX * (DCH*DCH);
    const __nv_bfloat16* __restrict__ wl = g_Wtl + WIDX * (DCH*DCH);

    float acc[8][4];
#pragma unroll
    for (int nt = 0; nt < 8; nt++)
#pragma unroll
        for (int c = 0; c < 4; c++) acc[nt][c] = 0.f;

    auto fill = [&](int s) {
        char* base = smem + (s & 1) * PJ_STAGE_S;
#pragma unroll
        for (int q = 0; q < 2; q++) {
            int c = t + q * 256;
            int hl = c >> 8, row = (c >> 2) & 63, col = c & 3;
            const __nv_bfloat16* src = hl ? al : ah;
            cp16(base + hl * PJ_A_T + row * PJ_RS + col * 16,
                 src + (size_t)(row0 + row) * DCH + s * 32 + col * 8);
        }
        const __nv_bfloat16* wsrc[2] = {wh, wl};
#pragma unroll
        for (int q = 0; q < 4; q++) {
            int c = t + q * 256;
            int m = c >> 9, n = (c >> 2) & 127, col = c & 3;
            cp16(base + 2 * PJ_A_T + m * PJ_B_T + n * PJ_RS + col * 16,
                 wsrc[m] + n * DCH + s * 32 + col * 8);
        }
    };

    fill(0); asm volatile("cp.async.commit_group;");
    fill(1); asm volatile("cp.async.commit_group;");

    const uint32_t aOff = (uint32_t)((wm * 16 + (lane & 15)) * PJ_RS + ((lane >> 4) << 4));
    const uint32_t bOff = (uint32_t)((wn * 64 + (lane & 15)) * PJ_RS + ((lane >> 4) << 4));

    for (int s = 0; s < 4; s++) {
        asm volatile("cp.async.wait_group 1;");
        __syncthreads();
        const uint32_t sb = sbase + (s & 1) * PJ_STAGE_S;
#pragma unroll
        for (int kh = 0; kh < 2; kh++) {
            uint32_t aH[4], aL[4];
            ldsm_x4(aH, sb + aOff + kh * 32);
            ldsm_x4(aL, sb + PJ_A_T + aOff + kh * 32);
#pragma unroll
            for (int ntp = 0; ntp < 4; ntp++) {
                const uint32_t bo = bOff + ntp * 16 * PJ_RS + kh * 32;
                uint32_t bH[4], bL[4];
                ldsm_x4(bH, sb + 2*PJ_A_T + bo);
                ldsm_x4(bL, sb + 2*PJ_A_T + PJ_B_T + bo);
                mma3(acc[2*ntp  ], aH, aL, bH[0], bH[2], bL[0], bL[2]);
                mma3(acc[2*ntp+1], aH, aL, bH[1], bH[3], bL[1], bL[3]);
            }
        }
        __syncthreads();
        if (s + 2 < 4) fill(s + 2);
        asm volatile("cp.async.commit_group;");
    }

    const int g  = lane >> 2;
    const int kc = (lane & 3) * 2;
    const int ra = row0 + wm * 16 + g, rb = ra + 8;
#pragma unroll
    for (int nt = 0; nt < 8; nt++) {
        const int col = wn * 64 + nt * 8 + kc;
        const float b0 = bias[col], b1 = bias[col + 1];
        float2 oa, ob;
        oa.x = acc[nt][0] + b0; oa.y = acc[nt][1] + b1;
        ob.x = acc[nt][2] + b0; ob.y = acc[nt][3] + b1;
        if (EPI == 1) { oa.x = fsig(oa.x); oa.y = fsig(oa.y);
                        ob.x = fsig(ob.x); ob.y = fsig(ob.y); }
        *reinterpret_cast<float2*>(&dst[(size_t)ra * DCH + col]) = oa;
        *reinterpret_cast<float2*>(&dst[(size_t)rb * DCH + col]) = ob;
    }
}

// ---------------------------------------------------------------------------
// K4: einsum via mma.sync. 2-stage ring (fill-after-compute, uniform commits),
// 3 CTAs/SM, B fragments via ldsm_x4 (nt-pairs). Tile 128i x 64k per CTA.
// ---------------------------------------------------------------------------
#define EM_RS     80
#define EM_A_T    (128 * EM_RS)             // 10240
#define EM_B_T    (64 * EM_RS)              // 5120
#define EM_STAGE  (2 * EM_A_T + 2 * EM_B_T) // 30720
#define EM_SMEM   (2 * EM_STAGE)            // 61440

__global__ __launch_bounds__(256, 3) void einsum_mma_kernel()
{
    extern __shared__ char smem[];
    const uint32_t sbase = (uint32_t)__cvta_generic_to_shared(smem);
    const int t    = threadIdx.x;
    const int lane = t & 31;
    const int wid  = t >> 5;
    const int wm   = wid & 3;
    const int wn   = wid >> 2;

    const int bid = blockIdx.x;
    const int d   = bid >> 5;
    const int i0  = ((bid >> 3) & 3) * 128;
    const int k0  = (bid & 7) * 64;

    const __nv_bfloat16* __restrict__ pLh = g_Lh + (size_t)d * NPOS + (size_t)i0 * NRES;
    const __nv_bfloat16* __restrict__ pLl = g_Ll + (size_t)d * NPOS + (size_t)i0 * NRES;
    const __nv_bfloat16* __restrict__ pRh = g_Rh + (size_t)d * NPOS + (size_t)k0 * NRES;
    const __nv_bfloat16* __restrict__ pRl = g_Rl + (size_t)d * NPOS + (size_t)k0 * NRES;

    float acc[2][4][4];
#pragma unroll
    for (int mt = 0; mt < 2; mt++)
#pragma unroll
        for (int nt = 0; nt < 4; nt++)
#pragma unroll
            for (int c = 0; c < 4; c++) acc[mt][nt][c] = 0.0f;

    auto fill = [&](int s) {
        char* base = smem + (s & 1) * EM_STAGE;
        const int j0s = s * 32;
        {
            int c0 = t, c1 = t + 256;
            int r0 = c0 >> 2, r1 = c1 >> 2, col0 = c0 & 3, col1 = c1 & 3;
            cp16(base + r0 * EM_RS + col0 * 16,
                 pLh + (size_t)r0 * NRES + j0s + col0 * 8);
            cp16(base + r1 * EM_RS + col1 * 16,
                 pLh + (size_t)r1 * NRES + j0s + col1 * 8);
            cp16(base + EM_A_T + r0 * EM_RS + col0 * 16,
                 pLl + (size_t)r0 * NRES + j0s + col0 * 8);
            cp16(base + EM_A_T + r1 * EM_RS + col1 * 16,
                 pLl + (size_t)r1 * NRES + j0s + col1 * 8);
        }
        {
            int r = t >> 2, col = t & 3;
            cp16(base + 2 * EM_A_T + r * EM_RS + col * 16,
                 pRh + (size_t)r * NRES + j0s + col * 8);
            cp16(base + 2 * EM_A_T + EM_B_T + r * EM_RS + col * 16,
                 pRl + (size_t)r * NRES + j0s + col * 8);
        }
    };

    fill(0); asm volatile("cp.async.commit_group;");
    fill(1); asm volatile("cp.async.commit_group;");

    // proj-style fragment addressing (m16/n16 x k16 via ldsm_x4)
    const uint32_t aOff = (uint32_t)(((lane & 15)) * EM_RS + ((lane >> 4) << 4));
    const uint32_t bOff = (uint32_t)((wn * 32 + (lane & 15)) * EM_RS + ((lane >> 4) << 4));

    for (int s = 0; s < 16; s++) {
        asm volatile("cp.async.wait_group 1;");
        __syncthreads();                  // stage s resident; all warps past s-1

        const uint32_t sb  = sbase + (s & 1) * EM_STAGE;
        const uint32_t aHb = sb, aLb = sb + EM_A_T;
        const uint32_t bHb = sb + 2 * EM_A_T, bLb = bHb + EM_B_T;

#pragma unroll
        for (int kh = 0; kh < 2; kh++) {
            const uint32_t kb = kh * 32;
            uint32_t aH[2][4], aL[2][4];
#pragma unroll
            for (int mt = 0; mt < 2; mt++) {
                const uint32_t am = (uint32_t)((wm * 32 + mt * 16) * EM_RS);
                ldsm_x4(aH[mt], aHb + am + aOff + kb);
                ldsm_x4(aL[mt], aLb + am + aOff + kb);
            }
#pragma unroll
            for (int ntp = 0; ntp < 2; ntp++) {
                const uint32_t nb = bOff + (uint32_t)(ntp * 16 * EM_RS) + kb;
                uint32_t bH[4], bL[4];
                ldsm_x4(bH, bHb + nb);
                ldsm_x4(bL, bLb + nb);
#pragma unroll
                for (int mt = 0; mt < 2; mt++) {
                    mma3(acc[mt][2*ntp  ], aH[mt], aL[mt], bH[0], bH[2], bL[0], bL[2]);
                    mma3(acc[mt][2*ntp+1], aH[mt], aL[mt], bH[1], bH[3], bL[1], bL[3]);
                }
            }
        }
        __syncthreads();                  // all warps done with buffer s&1
        if (s + 2 < 16) fill(s + 2);
        asm volatile("cp.async.commit_group;");   // uniform group count (tail-safe)
    }

    float* __restrict__ pOut = g_pret + (size_t)d * NPOS;
    const int g  = lane >> 2;
    const int kc = (lane & 3) * 2;
#pragma unroll
    for (int mt = 0; mt < 2; mt++) {
#pragma unroll
        for (int nt = 0; nt < 4; nt++) {
            const int i = i0 + wm * 32 + mt * 16 + g;
            const int k = k0 + wn * 32 + nt * 8 + kc;
            *reinterpret_cast<float2*>(&pOut[(size_t)i * NRES + k]) =
                make_float2(acc[mt][nt][0], acc[mt][nt][1]);
            *reinterpret_cast<float2*>(&pOut[(size_t)(i + 8) * NRES + k]) =
                make_float2(acc[mt][nt][2], acc[mt][nt][3]);
        }
    }
}

// ---------------------------------------------------------------------------
// T3: pre = pret^T * gate -> split into Ph/Pl bf16 [pos][d] (reuses g_Lh/g_Ll)
// ---------------------------------------------------------------------------
__global__ __launch_bounds__(256) void fuse_gate_kernel()
{
    __shared__ float sP[32][128];
    const int t = threadIdx.x;
    const size_t pos0 = (size_t)blockIdx.x * 32;
    const int d = t >> 1, h = (t & 1) * 16;
#pragma unroll
    for (int q = 0; q < 4; q++) {
        float4 v = reinterpret_cast<const float4*>(g_pret)[
            ((size_t)d * NPOS + pos0 + h) / 4 + q];
        sP[h + q*4 + 0][d] = v.x;
        sP[h + q*4 + 1][d] = v.y;
        sP[h + q*4 + 2][d] = v.z;
        sP[h + q*4 + 3][d] = v.w;
    }
    __syncthreads();
#pragma unroll
    for (int q = 0; q < 4; q++) {
        int idx = t + q * 256;
        int row = idx >> 5, c4 = idx & 31;
        float4 p = *reinterpret_cast<float4*>(&sP[row][c4 * 4]);
        float4 g = reinterpret_cast<const float4*>(g_gate)[(pos0 + row) * 32 + c4];
        p.x *= g.x; p.y *= g.y; p.z *= g.z; p.w *= g.w;
        __nv_bfloat16 h0,l0,h1,l1,h2,l2,h3,l3;
        bsplit(p.x,h0,l0); bsplit(p.y,h1,l1); bsplit(p.z,h2,l2); bsplit(p.w,h3,l3);
        const size_t o = (pos0 + row) * DCH + c4 * 4;
        *reinterpret_cast<uint2*>(&g_Lh[o]) = make_uint2(pack2(h0,h1), pack2(h2,h3));
        *reinterpret_cast<uint2*>(&g_Ll[o]) = make_uint2(pack2(l0,l1), pack2(l2,l3));
    }
}

// ---------------------------------------------------------------------------
extern "C" void kernel_launch(void* const* d_in, const int* in_sizes, int n_in,
                              void* d_out, int out_size)
{
    (void)in_sizes; (void)n_in; (void)out_size;
    const float* pair = (const float*)d_in[0];
    const float* mask = (const float*)d_in[1];
    const float* ln_g = (const float*)d_in[2];
    const float* ln_b = (const float*)d_in[3];
    const float* w_lp = (const float*)d_in[4];
    const float* b_lp = (const float*)d_in[5];
    const float* w_lg = (const float*)d_in[6];
    const float* b_lg = (const float*)d_in[7];
    const float* w_rp = (const float*)d_in[8];
    const float* b_rp = (const float*)d_in[9];
    const float* w_rg = (const float*)d_in[10];
    const float* b_rg = (const float*)d_in[11];
    const float* w_g  = (const float*)d_in[12];
    const float* b_g  = (const float*)d_in[13];
    const float* w_o  = (const float*)d_in[14];
    const float* b_o  = (const float*)d_in[15];
    float* out = (float*)d_out;

    cudaFuncSetAttribute(einsum_mma_kernel,
                         cudaFuncAttributeMaxDynamicSharedMemorySize, EM_SMEM);
    cudaFuncSetAttribute(proj_dual_mma<0,1,0>,
                         cudaFuncAttributeMaxDynamicSharedMemorySize, PJ_SMEM_D);
    cudaFuncSetAttribute(proj_dual_mma<2,3,1>,
                         cudaFuncAttributeMaxDynamicSharedMemorySize, PJ_SMEM_D);
    cudaFuncSetAttribute(proj_single_mma<4,1>,
                         cudaFuncAttributeMaxDynamicSharedMemorySize, PJ_SMEM_S);
    cudaFuncSetAttribute(proj_single_mma<5,0>,
                         cudaFuncAttributeMaxDynamicSharedMemorySize, PJ_SMEM_S);

    prep_weights<<<6, 256>>>(w_lp, w_lg, w_rp, w_rg, w_g, w_o);
    ln_split_kernel<<<NPOS / 8, 256>>>(pair, ln_g, ln_b);
    proj_dual_mma<0,1,0><<<NPOS / 64, 256, PJ_SMEM_D>>>(b_lp, b_lg, mask);
    proj_dual_mma<2,3,1><<<NPOS / 64, 256, PJ_SMEM_D>>>(b_rp, b_rg, mask);
    proj_single_mma<4,1><<<NPOS / 64, 256, PJ_SMEM_S>>>(b_g, nullptr);
    einsum_mma_kernel<<<4096, 256, EM_SMEM>>>();
    fuse_gate_kernel<<<NPOS / 32, 256>>>();
    proj_single_mma<5,0><<<NPOS / 64, 256, PJ_SMEM_S>>>(b_o, out);
}

// round 13
// speedup vs baseline: 1.1529x; 1.1271x over previous
#include <cuda_runtime.h>
#include <cuda_bf16.h>
#include <cstdint>

#define NRES 512
#define DCH  128
#define NPOS (NRES*NRES)

// Scratch (device globals — no runtime allocation allowed)
__device__ float g_gate [(size_t)NPOS * DCH];
__device__ float g_pret [(size_t)NPOS * DCH];        // [d][i][k]
__device__ __nv_bfloat16 g_Xh[(size_t)NPOS * DCH];   // LN(x) split, [pos][d]
__device__ __nv_bfloat16 g_Xl[(size_t)NPOS * DCH];
__device__ __nv_bfloat16 g_Lh[(size_t)DCH * NPOS];   // [d][i][j]; later pre-split [pos][d]
__device__ __nv_bfloat16 g_Ll[(size_t)DCH * NPOS];
__device__ __nv_bfloat16 g_Rh[(size_t)DCH * NPOS];   // [d][k][j]
__device__ __nv_bfloat16 g_Rl[(size_t)DCH * NPOS];
__device__ __nv_bfloat16 g_Wth[6 * DCH * DCH];       // W^T hi, [widx][n][k]
__device__ __nv_bfloat16 g_Wtl[6 * DCH * DCH];       // W^T lo

__device__ __forceinline__ float fsig(float x) { return 1.0f / (1.0f + __expf(-x)); }

__device__ __forceinline__ void cp16(void* s, const void* g) {
    unsigned sa = (unsigned)__cvta_generic_to_shared(s);
    asm volatile("cp.async.cg.shared.global [%0], [%1], 16;" :: "r"(sa), "l"(g));
}

// ---- mma.sync / ldmatrix (sm_80-class PTX: compiles on plain sm_103) ------
__device__ __forceinline__ void ldsm_x4(uint32_t* r, uint32_t addr) {
    asm volatile("ldmatrix.sync.aligned.m8n8.x4.shared.b16 {%0,%1,%2,%3}, [%4];"
        : "=r"(r[0]), "=r"(r[1]), "=r"(r[2]), "=r"(r[3]) : "r"(addr));
}
__device__ __forceinline__ void ldsm_x2(uint32_t* r, uint32_t addr) {
    asm volatile("ldmatrix.sync.aligned.m8n8.x2.shared.b16 {%0,%1}, [%2];"
        : "=r"(r[0]), "=r"(r[1]) : "r"(addr));
}
__device__ __forceinline__ void mma16816(float* c, const uint32_t* a, const uint32_t* b) {
    asm volatile("mma.sync.aligned.m16n8k16.row.col.f32.bf16.bf16.f32 "
        "{%0,%1,%2,%3}, {%4,%5,%6,%7}, {%8,%9}, {%0,%1,%2,%3};"
        : "+f"(c[0]), "+f"(c[1]), "+f"(c[2]), "+f"(c[3])
        : "r"(a[0]), "r"(a[1]), "r"(a[2]), "r"(a[3]), "r"(b[0]), "r"(b[1]));
}
// C += Ah*Bh + Ah*Bl + Al*Bh   (bf16 hi/lo split product)
__device__ __forceinline__ void mma3(float* c, const uint32_t* aH, const uint32_t* aL,
                                     uint32_t bh0, uint32_t bh1,
                                     uint32_t bl0, uint32_t bl1) {
    uint32_t b[2];
    b[0] = bh0; b[1] = bh1; mma16816(c, aH, b);
    b[0] = bl0; b[1] = bl1; mma16816(c, aH, b);
    b[0] = bh0; b[1] = bh1; mma16816(c, aL, b);
}
// C += Ah*Bh only (single product; used for sigmoid-gate logits)
__device__ __forceinline__ void mma1(float* c, const uint32_t* aH,
                                     uint32_t b0, uint32_t b1) {
    uint32_t b[2];
    b[0] = b0; b[1] = b1; mma16816(c, aH, b);
}

__device__ __forceinline__ void bsplit(float v, __nv_bfloat16& h, __nv_bfloat16& l) {
    h = __float2bfloat16(v);
    l = __float2bfloat16(v - __bfloat162float(h));
}
__device__ __forceinline__ uint32_t pack2(__nv_bfloat16 a, __nv_bfloat16 b) {
    __nv_bfloat162 p(a, b);
    return *reinterpret_cast<uint32_t*>(&p);
}

// ---------------------------------------------------------------------------
// K0: weight prep — W[k][n] -> Wt_h/Wt_l[n][k] bf16. One block per matrix.
// ---------------------------------------------------------------------------
__global__ void prep_weights(const float* w0, const float* w1, const float* w2,
                             const float* w3, const float* w4, const float* w5)
{
    const float* srcs[6] = {w0, w1, w2, w3, w4, w5};
    const float* src = srcs[blockIdx.x];
    const int base = blockIdx.x * DCH * DCH;
    for (int idx = threadIdx.x; idx < DCH * DCH; idx += blockDim.x) {
        int k = idx >> 7, n = idx & 127;
        __nv_bfloat16 h, l;
        bsplit(src[idx], h, l);
        g_Wth[base + n * DCH + k] = h;
        g_Wtl[base + n * DCH + k] = l;
    }
}

// ---------------------------------------------------------------------------
// K1: LayerNorm over D=128 -> Xh/Xl bf16 [pos][d].
// ---------------------------------------------------------------------------
__global__ void ln_split_kernel(const float* __restrict__ pair,
                                const float* __restrict__ lng,
                                const float* __restrict__ lnb)
{
    const int lane = threadIdx.x & 31;
    const int row  = blockIdx.x * 8 + (threadIdx.x >> 5);
    const float4 v = reinterpret_cast<const float4*>(pair)[(size_t)row * 32 + lane];
    float s = v.x + v.y + v.z + v.w;
    float q = v.x*v.x + v.y*v.y + v.z*v.z + v.w*v.w;
#pragma unroll
    for (int o = 16; o > 0; o >>= 1) {
        s += __shfl_xor_sync(0xffffffffu, s, o);
        q += __shfl_xor_sync(0xffffffffu, q, o);
    }
    const float mean = s * (1.0f / 128.0f);
    const float var  = q * (1.0f / 128.0f) - mean * mean;
    const float rs   = rsqrtf(var + 1e-5f);
    const float4 g4 = reinterpret_cast<const float4*>(lng)[lane];
    const float4 b4 = reinterpret_cast<const float4*>(lnb)[lane];
    float o0 = (v.x - mean) * rs * g4.x + b4.x;
    float o1 = (v.y - mean) * rs * g4.y + b4.y;
    float o2 = (v.z - mean) * rs * g4.z + b4.z;
    float o3 = (v.w - mean) * rs * g4.w + b4.w;
    __nv_bfloat16 h0,l0,h1,l1,h2,l2,h3,l3;
    bsplit(o0,h0,l0); bsplit(o1,h1,l1); bsplit(o2,h2,l2); bsplit(o3,h3,l3);
    uint2 hv = make_uint2(pack2(h0,h1), pack2(h2,h3));
    uint2 lv = make_uint2(pack2(l0,l1), pack2(l2,l3));
    *reinterpret_cast<uint2*>(&g_Xh[(size_t)row * DCH + lane * 4]) = hv;
    *reinterpret_cast<uint2*>(&g_Xl[(size_t)row * DCH + lane * 4]) = lv;
}

// ---------------------------------------------------------------------------
// Projection GEMMs on mma.sync. M tile 64 x N 128, K=128 in 4 stages of 32.
// 8 warps = 4M x 2N, warp = 16 rows x 64 cols.
// ---------------------------------------------------------------------------
#define PJ_RS      80
#define PJ_A_T     (64 * PJ_RS)               // 5120
#define PJ_B_T     (128 * PJ_RS)              // 10240
#define PJ_STAGE_D (2*PJ_A_T + 3*PJ_B_T)      // 40960 (P hi/lo + G hi only)
#define PJ_SMEM_D  (2 * PJ_STAGE_D)           // 81920
#define PJ_STAGE_S3 (2*PJ_A_T + 2*PJ_B_T)     // 30720
#define PJ_SMEM_S3  (2 * PJ_STAGE_S3)         // 61440
#define PJ_STAGE_S1 (PJ_A_T + PJ_B_T)         // 15360
#define PJ_SMEM_S1  (2 * PJ_STAGE_S1)         // 30720

// dual: v = (X@Wp + bp) * sigmoid(X@Wg + bg) * mask, then hi/lo split + transpose
// P-side: full 3-product precision. G-side: single bf16 product (sigmoid
// attenuates the error; see theory). DST 0 -> g_Lh/g_Ll [d][i][j];
// DST 1 -> g_Rh/g_Rl [d][k][j].
template<int WP, int WG, int DST>
__global__ __launch_bounds__(256, 2) void proj_dual_mma(
    const float* __restrict__ bp, const float* __restrict__ bg,
    const float* __restrict__ mask)
{
    extern __shared__ char smem[];
    const uint32_t sbase = (uint32_t)__cvta_generic_to_shared(smem);
    const int t = threadIdx.x, lane = t & 31, wid = t >> 5;
    const int wm = wid & 3, wn = wid >> 2;

    // row mapping
    const int row0 = blockIdx.x * 64;          // DST==0
    const int kk   = blockIdx.x >> 3;          // DST==1
    const int j0   = (blockIdx.x & 7) * 64;    // DST==1

    auto apos = [&](int row) -> size_t {
        if (DST == 0) return (size_t)(row0 + row);
        else          return (size_t)(j0 + row) * NRES + kk;
    };

    const __nv_bfloat16* __restrict__ wph = g_Wth + WP * (DCH*DCH);
    const __nv_bfloat16* __restrict__ wpl = g_Wtl + WP * (DCH*DCH);
    const __nv_bfloat16* __restrict__ wgh = g_Wth + WG * (DCH*DCH);

    float accP[8][4], accG[8][4];
#pragma unroll
    for (int nt = 0; nt < 8; nt++)
#pragma unroll
        for (int c = 0; c < 4; c++) { accP[nt][c] = 0.f; accG[nt][c] = 0.f; }

    auto fill = [&](int s) {
        char* base = smem + (s & 1) * PJ_STAGE_D;
#pragma unroll
        for (int q = 0; q < 2; q++) {           // A: Xh, Xl
            int c = t + q * 256;
            int hl = c >> 8, row = (c >> 2) & 63, col = c & 3;
            const __nv_bfloat16* src = hl ? g_Xl : g_Xh;
            cp16(base + hl * PJ_A_T + row * PJ_RS + col * 16,
                 src + apos(row) * DCH + s * 32 + col * 8);
        }
        const __nv_bfloat16* wsrc[3] = {wph, wpl, wgh};
#pragma unroll
        for (int q = 0; q < 6; q++) {           // B: ph, pl, gh
            int c = t + q * 256;
            int m = c >> 9, n = (c >> 2) & 127, col = c & 3;
            cp16(base + 2 * PJ_A_T + m * PJ_B_T + n * PJ_RS + col * 16,
                 wsrc[m] + n * DCH + s * 32 + col * 8);
        }
    };

    fill(0); asm volatile("cp.async.commit_group;");
    fill(1); asm volatile("cp.async.commit_group;");

    const uint32_t aOff = (uint32_t)((wm * 16 + (lane & 15)) * PJ_RS + ((lane >> 4) << 4));
    const uint32_t bOff = (uint32_t)((wn * 64 + (lane & 15)) * PJ_RS + ((lane >> 4) << 4));

    for (int s = 0; s < 4; s++) {
        asm volatile("cp.async.wait_group 1;");
        __syncthreads();
        const uint32_t sb = sbase + (s & 1) * PJ_STAGE_D;
#pragma unroll
        for (int kh = 0; kh < 2; kh++) {
            uint32_t aH[4], aL[4];
            ldsm_x4(aH, sb + aOff + kh * 32);
            ldsm_x4(aL, sb + PJ_A_T + aOff + kh * 32);
#pragma unroll
            for (int ntp = 0; ntp < 4; ntp++) {
                const uint32_t bo = bOff + ntp * 16 * PJ_RS + kh * 32;
                uint32_t pH[4], pL[4], gH[4];
                ldsm_x4(pH, sb + 2*PJ_A_T + bo);
                ldsm_x4(pL, sb + 2*PJ_A_T + PJ_B_T + bo);
                ldsm_x4(gH, sb + 2*PJ_A_T + 2*PJ_B_T + bo);
                mma3(accP[2*ntp  ], aH, aL, pH[0], pH[2], pL[0], pL[2]);
                mma3(accP[2*ntp+1], aH, aL, pH[1], pH[3], pL[1], pL[3]);
                mma1(accG[2*ntp  ], aH, gH[0], gH[2]);
                mma1(accG[2*ntp+1], aH, gH[1], gH[3]);
            }
        }
        __syncthreads();                 // all warps done reading buffer s&1
        if (s + 2 < 4) fill(s + 2);
        asm volatile("cp.async.commit_group;");
    }

    // ---- Epilogue: gated value -> smem fp32 [64][129] -> bf16 hi/lo, d-major
    float* sP = reinterpret_cast<float*>(smem);   // 64*129*4 = 33024 B, fits
    const int g  = lane >> 2;
    const int kc = (lane & 3) * 2;
    const int ra = wm * 16 + g, rb = ra + 8;      // tile-local rows
    const float ma = mask[apos(ra)];
    const float mb = mask[apos(rb)];
#pragma unroll
    for (int nt = 0; nt < 8; nt++) {
        const int col = wn * 64 + nt * 8 + kc;
        const float bp0 = bp[col], bp1 = bp[col + 1];
        const float bg0 = bg[col], bg1 = bg[col + 1];
        sP[ra * 129 + col    ] = (accP[nt][0] + bp0) * fsig(accG[nt][0] + bg0) * ma;
        sP[ra * 129 + col + 1] = (accP[nt][1] + bp1) * fsig(accG[nt][1] + bg1) * ma;
        sP[rb * 129 + col    ] = (accP[nt][2] + bp0) * fsig(accG[nt][2] + bg0) * mb;
        sP[rb * 129 + col + 1] = (accP[nt][3] + bp1) * fsig(accG[nt][3] + bg1) * mb;
    }
    __syncthreads();
    // thread t: channel dch = t>>1, rows h..h+31 (h = 0 or 32)
    const int dch = t >> 1, h = (t & 1) * 32;
    uint32_t wh[16], wl[16];
#pragma unroll
    for (int q = 0; q < 16; q++) {
        __nv_bfloat16 h0, l0, h1, l1;
        bsplit(sP[(h + 2*q    ) * 129 + dch], h0, l0);
        bsplit(sP[(h + 2*q + 1) * 129 + dch], h1, l1);
        wh[q] = pack2(h0, h1);
        wl[q] = pack2(l0, l1);
    }
    size_t ob;
    if (DST == 0) ob = (size_t)dch * NPOS + row0 + h;                     // [d][pos]
    else          ob = (size_t)dch * NPOS + (size_t)kk * NRES + j0 + h;   // [d][k][j]
    __nv_bfloat16* __restrict__ dH = DST ? g_Rh : g_Lh;
    __nv_bfloat16* __restrict__ dL = DST ? g_Rl : g_Ll;
#pragma unroll
    for (int q = 0; q < 4; q++) {
        *reinterpret_cast<uint4*>(&dH[ob + q * 8]) =
            make_uint4(wh[q*4], wh[q*4+1], wh[q*4+2], wh[q*4+3]);
        *reinterpret_cast<uint4*>(&dL[ob + q * 8]) =
            make_uint4(wl[q*4], wl[q*4+1], wl[q*4+2], wl[q*4+3]);
    }
}

// single 3-product: out = PRE@W + b  (full precision; feeds output directly)
template<int WIDX>
__global__ __launch_bounds__(256, 2) void proj_single3_mma(
    const float* __restrict__ bias, float* __restrict__ dst)
{
    extern __shared__ char smem[];
    const uint32_t sbase = (uint32_t)__cvta_generic_to_shared(smem);
    const int t = threadIdx.x, lane = t & 31, wid = t >> 5;
    const int wm = wid & 3, wn = wid >> 2;
    const int row0 = blockIdx.x * 64;
    const __nv_bfloat16* __restrict__ ah = g_Lh;   // pre-split hi
    const __nv_bfloat16* __restrict__ al = g_Ll;   // pre-split lo

    const __nv_bfloat16* __restrict__ wh = g_Wth + WIDX * (DCH*DCH);
    const __nv_bfloat16* __restrict__ wl = g_Wtl + WIDX * (DCH*DCH);

    float acc[8][4];
#pragma unroll
    for (int nt = 0; nt < 8; nt++)
#pragma unroll
        for (int c = 0; c < 4; c++) acc[nt][c] = 0.f;

    auto fill = [&](int s) {
        char* base = smem + (s & 1) * PJ_STAGE_S3;
#pragma unroll
        for (int q = 0; q < 2; q++) {
            int c = t + q * 256;
            int hl = c >> 8, row = (c >> 2) & 63, col = c & 3;
            const __nv_bfloat16* src = hl ? al : ah;
            cp16(base + hl * PJ_A_T + row * PJ_RS + col * 16,
                 src + (size_t)(row0 + row) * DCH + s * 32 + col * 8);
        }
        const __nv_bfloat16* wsrc[2] = {wh, wl};
#pragma unroll
        for (int q = 0; q < 4; q++) {
            int c = t + q * 256;
            int m = c >> 9, n = (c >> 2) & 127, col = c & 3;
            cp16(base + 2 * PJ_A_T + m * PJ_B_T + n * PJ_RS + col * 16,
                 wsrc[m] + n * DCH + s * 32 + col * 8);
        }
    };

    fill(0); asm volatile("cp.async.commit_group;");
    fill(1); asm volatile("cp.async.commit_group;");

    const uint32_t aOff = (uint32_t)((wm * 16 + (lane & 15)) * PJ_RS + ((lane >> 4) << 4));
    const uint32_t bOff = (uint32_t)((wn * 64 + (lane & 15)) * PJ_RS + ((lane >> 4) << 4));

    for (int s = 0; s < 4; s++) {
        asm volatile("cp.async.wait_group 1;");
        __syncthreads();
        const uint32_t sb = sbase + (s & 1) * PJ_STAGE_S3;
#pragma unroll
        for (int kh = 0; kh < 2; kh++) {
            uint32_t aH[4], aL[4];
            ldsm_x4(aH, sb + aOff + kh * 32);
            ldsm_x4(aL, sb + PJ_A_T + aOff + kh * 32);
#pragma unroll
            for (int ntp = 0; ntp < 4; ntp++) {
                const uint32_t bo = bOff + ntp * 16 * PJ_RS + kh * 32;
                uint32_t bH[4], bL[4];
                ldsm_x4(bH, sb + 2*PJ_A_T + bo);
                ldsm_x4(bL, sb + 2*PJ_A_T + PJ_B_T + bo);
                mma3(acc[2*ntp  ], aH, aL, bH[0], bH[2], bL[0], bL[2]);
                mma3(acc[2*ntp+1], aH, aL, bH[1], bH[3], bL[1], bL[3]);
            }
        }
        __syncthreads();
        if (s + 2 < 4) fill(s + 2);
        asm volatile("cp.async.commit_group;");
    }

    const int g  = lane >> 2;
    const int kc = (lane & 3) * 2;
    const int ra = row0 + wm * 16 + g, rb = ra + 8;
#pragma unroll
    for (int nt = 0; nt < 8; nt++) {
        const int col = wn * 64 + nt * 8 + kc;
        const float b0 = bias[col], b1 = bias[col + 1];
        float2 oa, ob;
        oa.x = acc[nt][0] + b0; oa.y = acc[nt][1] + b1;
        ob.x = acc[nt][2] + b0; ob.y = acc[nt][3] + b1;
        *reinterpret_cast<float2*>(&dst[(size_t)ra * DCH + col]) = oa;
        *reinterpret_cast<float2*>(&dst[(size_t)rb * DCH + col]) = ob;
    }
}

// single 1-product: g_gate = sigmoid(Xh@Wh + b). Half the loads, 1/3 the MACs.
template<int WIDX>
__global__ __launch_bounds__(256, 3) void proj_gate1_mma(
    const float* __restrict__ bias)
{
    extern __shared__ char smem[];
    const uint32_t sbase = (uint32_t)__cvta_generic_to_shared(smem);
    const int t = threadIdx.x, lane = t & 31, wid = t >> 5;
    const int wm = wid & 3, wn = wid >> 2;
    const int row0 = blockIdx.x * 64;

    const __nv_bfloat16* __restrict__ wh = g_Wth + WIDX * (DCH*DCH);

    float acc[8][4];
#pragma unroll
    for (int nt = 0; nt < 8; nt++)
#pragma unroll
        for (int c = 0; c < 4; c++) acc[nt][c] = 0.f;

    auto fill = [&](int s) {
        char* base = smem + (s & 1) * PJ_STAGE_S1;
        {   // A: Xh only — 256 chunks
            int row = t >> 2, col = t & 3;
            cp16(base + row * PJ_RS + col * 16,
                 g_Xh + (size_t)(row0 + row) * DCH + s * 32 + col * 8);
        }
#pragma unroll
        for (int q = 0; q < 2; q++) {   // B: Wh only — 512 chunks
            int c = t + q * 256;
            int n = (c >> 2) & 127, col = c & 3;
            cp16(base + PJ_A_T + n * PJ_RS + col * 16,
                 wh + n * DCH + s * 32 + col * 8);
        }
    };

    fill(0); asm volatile("cp.async.commit_group;");
    fill(1); asm volatile("cp.async.commit_group;");

    const uint32_t aOff = (uint32_t)((wm * 16 + (lane & 15)) * PJ_RS + ((lane >> 4) << 4));
    const uint32_t bOff = (uint32_t)((wn * 64 + (lane & 15)) * PJ_RS + ((lane >> 4) << 4));

    for (int s = 0; s < 4; s++) {
        asm volatile("cp.async.wait_group 1;");
        __syncthreads();
        const uint32_t sb = sbase + (s & 1) * PJ_STAGE_S1;
#pragma unroll
        for (int kh = 0; kh < 2; kh++) {
            uint32_t aH[4];
            ldsm_x4(aH, sb + aOff + kh * 32);
#pragma unroll
            for (int ntp = 0; ntp < 4; ntp++) {
                const uint32_t bo = bOff + ntp * 16 * PJ_RS + kh * 32;
                uint32_t bH[4];
                ldsm_x4(bH, sb + PJ_A_T + bo);
                mma1(acc[2*ntp  ], aH, bH[0], bH[2]);
                mma1(acc[2*ntp+1], aH, bH[1], bH[3]);
            }
        }
        __syncthreads();
        if (s + 2 < 4) fill(s + 2);
        asm volatile("cp.async.commit_group;");
    }

    const int g  = lane >> 2;
    const int kc = (lane & 3) * 2;
    const int ra = row0 + wm * 16 + g, rb = ra + 8;
#pragma unroll
    for (int nt = 0; nt < 8; nt++) {
        const int col = wn * 64 + nt * 8 + kc;
        const float b0 = bias[col], b1 = bias[col + 1];
        float2 oa, ob;
        oa.x = fsig(acc[nt][0] + b0); oa.y = fsig(acc[nt][1] + b1);
        ob.x = fsig(acc[nt][2] + b0); ob.y = fsig(acc[nt][3] + b1);
        *reinterpret_cast<float2*>(&g_gate[(size_t)ra * DCH + col]) = oa;
        *reinterpret_cast<float2*>(&g_gate[(size_t)rb * DCH + col]) = ob;
    }
}

// ---------------------------------------------------------------------------
// K4: einsum via mma.sync (R8-R10, proven — 3-stage ring, unchanged).
// ---------------------------------------------------------------------------
#define EM_RS     80
#define EM_A_T    (128 * EM_RS)
#define EM_B_T    (64 * EM_RS)
#define EM_STAGE  (2 * EM_A_T + 2 * EM_B_T)
#define EM_SMEM   (3 * EM_STAGE)

__global__ __launch_bounds__(256, 2) void einsum_mma_kernel()
{
    extern __shared__ char smem[];
    const uint32_t sbase = (uint32_t)__cvta_generic_to_shared(smem);
    const int t    = threadIdx.x;
    const int lane = t & 31;
    const int wid  = t >> 5;
    const int wm   = wid & 3;
    const int wn   = wid >> 2;

    const int bid = blockIdx.x;
    const int d   = bid >> 5;
    const int i0  = ((bid >> 3) & 3) * 128;
    const int k0  = (bid & 7) * 64;

    const __nv_bfloat16* __restrict__ pLh = g_Lh + (size_t)d * NPOS + (size_t)i0 * NRES;
    const __nv_bfloat16* __restrict__ pLl = g_Ll + (size_t)d * NPOS + (size_t)i0 * NRES;
    const __nv_bfloat16* __restrict__ pRh = g_Rh + (size_t)d * NPOS + (size_t)k0 * NRES;
    const __nv_bfloat16* __restrict__ pRl = g_Rl + (size_t)d * NPOS + (size_t)k0 * NRES;

    float acc[2][4][4];
#pragma unroll
    for (int mt = 0; mt < 2; mt++)
#pragma unroll
        for (int nt = 0; nt < 4; nt++)
#pragma unroll
            for (int c = 0; c < 4; c++) acc[mt][nt][c] = 0.0f;

    auto fill = [&](int s) {
        const int buf = s % 3;
        char* base = smem + buf * EM_STAGE;
        const int j0s = s * 32;
        {
            int c0 = t, c1 = t + 256;
            int r0 = c0 >> 2, r1 = c1 >> 2, col0 = c0 & 3, col1 = c1 & 3;
            cp16(base + r0 * EM_RS + col0 * 16,
                 pLh + (size_t)r0 * NRES + j0s + col0 * 8);
            cp16(base + r1 * EM_RS + col1 * 16,
                 pLh + (size_t)r1 * NRES + j0s + col1 * 8);
            cp16(base + EM_A_T + r0 * EM_RS + col0 * 16,
                 pLl + (size_t)r0 * NRES + j0s + col0 * 8);
            cp16(base + EM_A_T + r1 * EM_RS + col1 * 16,
                 pLl + (size_t)r1 * NRES + j0s + col1 * 8);
        }
        {
            int r = t >> 2, col = t & 3;
            cp16(base + 2 * EM_A_T + r * EM_RS + col * 16,
                 pRh + (size_t)r * NRES + j0s + col * 8);
            cp16(base + 2 * EM_A_T + EM_B_T + r * EM_RS + col * 16,
                 pRl + (size_t)r * NRES + j0s + col * 8);
        }
    };

    fill(0); asm volatile("cp.async.commit_group;");
    fill(1); asm volatile("cp.async.commit_group;");

    const uint32_t aOff = (uint32_t)((wm * 32 + ((lane >> 3) & 1) * 8 + (lane & 7)) * EM_RS
                                     + ((lane >> 4) << 4));
    const uint32_t bOff = (uint32_t)((wn * 32 + (lane & 7)) * EM_RS
                                     + (((lane >> 3) & 1) << 4));

    for (int s = 0; s < 16; s++) {
        asm volatile("cp.async.wait_group 1;");
        __syncthreads();
        if (s + 2 < 16) fill(s + 2);
        asm volatile("cp.async.commit_group;");

        const uint32_t sb  = sbase + (s % 3) * EM_STAGE;
        const uint32_t aHb = sb, aLb = sb + EM_A_T;
        const uint32_t bHb = sb + 2 * EM_A_T, bLb = bHb + EM_B_T;

#pragma unroll
        for (int kh = 0; kh < 2; kh++) {
            const uint32_t kb = kh * 32;
            uint32_t aH[2][4], aL[2][4];
            ldsm_x4(aH[0], aHb + aOff + kb);
            ldsm_x4(aH[1], aHb + aOff + 16 * EM_RS + kb);
            ldsm_x4(aL[0], aLb + aOff + kb);
            ldsm_x4(aL[1], aLb + aOff + 16 * EM_RS + kb);
#pragma unroll
            for (int nt = 0; nt < 4; nt++) {
                uint32_t bH[2], bL[2];
                ldsm_x2(bH, bHb + bOff + nt * 8 * EM_RS + kb);
                ldsm_x2(bL, bLb + bOff + nt * 8 * EM_RS + kb);
#pragma unroll
                for (int mt = 0; mt < 2; mt++) {
                    mma16816(acc[mt][nt], aH[mt], bH);
                    mma16816(acc[mt][nt], aH[mt], bL);
                    mma16816(acc[mt][nt], aL[mt], bH);
                }
            }
        }
    }

    float* __restrict__ pOut = g_pret + (size_t)d * NPOS;
    const int g  = lane >> 2;
    const int kc = (lane & 3) * 2;
#pragma unroll
    for (int mt = 0; mt < 2; mt++) {
#pragma unroll
        for (int nt = 0; nt < 4; nt++) {
            const int i = i0 + wm * 32 + mt * 16 + g;
            const int k = k0 + wn * 32 + nt * 8 + kc;
            *reinterpret_cast<float2*>(&pOut[(size_t)i * NRES + k]) =
                make_float2(acc[mt][nt][0], acc[mt][nt][1]);
            *reinterpret_cast<float2*>(&pOut[(size_t)(i + 8) * NRES + k]) =
                make_float2(acc[mt][nt][2], acc[mt][nt][3]);
        }
    }
}

// ---------------------------------------------------------------------------
// T3: pre = pret^T * gate -> split into Ph/Pl bf16 [pos][d] (reuses g_Lh/g_Ll)
// ---------------------------------------------------------------------------
__global__ __launch_bounds__(256) void fuse_gate_kernel()
{
    __shared__ float sP[32][128];
    const int t = threadIdx.x;
    const size_t pos0 = (size_t)blockIdx.x * 32;
    const int d = t >> 1, h = (t & 1) * 16;
#pragma unroll
    for (int q = 0; q < 4; q++) {
        float4 v = reinterpret_cast<const float4*>(g_pret)[
            ((size_t)d * NPOS + pos0 + h) / 4 + q];
        sP[h + q*4 + 0][d] = v.x;
        sP[h + q*4 + 1][d] = v.y;
        sP[h + q*4 + 2][d] = v.z;
        sP[h + q*4 + 3][d] = v.w;
    }
    __syncthreads();
#pragma unroll
    for (int q = 0; q < 4; q++) {
        int idx = t + q * 256;
        int row = idx >> 5, c4 = idx & 31;
        float4 p = *reinterpret_cast<float4*>(&sP[row][c4 * 4]);
        float4 g = reinterpret_cast<const float4*>(g_gate)[(pos0 + row) * 32 + c4];
        p.x *= g.x; p.y *= g.y; p.z *= g.z; p.w *= g.w;
        __nv_bfloat16 h0,l0,h1,l1,h2,l2,h3,l3;
        bsplit(p.x,h0,l0); bsplit(p.y,h1,l1); bsplit(p.z,h2,l2); bsplit(p.w,h3,l3);
        const size_t o = (pos0 + row) * DCH + c4 * 4;
        *reinterpret_cast<uint2*>(&g_Lh[o]) = make_uint2(pack2(h0,h1), pack2(h2,h3));
        *reinterpret_cast<uint2*>(&g_Ll[o]) = make_uint2(pack2(l0,l1), pack2(l2,l3));
    }
}

// ---------------------------------------------------------------------------
extern "C" void kernel_launch(void* const* d_in, const int* in_sizes, int n_in,
                              void* d_out, int out_size)
{
    (void)in_sizes; (void)n_in; (void)out_size;
    const float* pair = (const float*)d_in[0];
    const float* mask = (const float*)d_in[1];
    const float* ln_g = (const float*)d_in[2];
    const float* ln_b = (const float*)d_in[3];
    const float* w_lp = (const float*)d_in[4];
    const float* b_lp = (const float*)d_in[5];
    const float* w_lg = (const float*)d_in[6];
    const float* b_lg = (const float*)d_in[7];
    const float* w_rp = (const float*)d_in[8];
    const float* b_rp = (const float*)d_in[9];
    const float* w_rg = (const float*)d_in[10];
    const float* b_rg = (const float*)d_in[11];
    const float* w_g  = (const float*)d_in[12];
    const float* b_g  = (const float*)d_in[13];
    const float* w_o  = (const float*)d_in[14];
    const float* b_o  = (const float*)d_in[15];
    float* out = (float*)d_out;

    cudaFuncSetAttribute(einsum_mma_kernel,
                         cudaFuncAttributeMaxDynamicSharedMemorySize, EM_SMEM);
    cudaFuncSetAttribute(proj_dual_mma<0,1,0>,
                         cudaFuncAttributeMaxDynamicSharedMemorySize, PJ_SMEM_D);
    cudaFuncSetAttribute(proj_dual_mma<2,3,1>,
                         cudaFuncAttributeMaxDynamicSharedMemorySize, PJ_SMEM_D);
    cudaFuncSetAttribute(proj_gate1_mma<4>,
                         cudaFuncAttributeMaxDynamicSharedMemorySize, PJ_SMEM_S1);
    cudaFuncSetAttribute(proj_single3_mma<5>,
                         cudaFuncAttributeMaxDynamicSharedMemorySize, PJ_SMEM_S3);

    prep_weights<<<6, 256>>>(w_lp, w_lg, w_rp, w_rg, w_g, w_o);
    ln_split_kernel<<<NPOS / 8, 256>>>(pair, ln_g, ln_b);
    proj_dual_mma<0,1,0><<<NPOS / 64, 256, PJ_SMEM_D>>>(b_lp, b_lg, mask);
    proj_dual_mma<2,3,1><<<NPOS / 64, 256, PJ_SMEM_D>>>(b_rp, b_rg, mask);
    proj_gate1_mma<4><<<NPOS / 64, 256, PJ_SMEM_S1>>>(b_g);
    einsum_mma_kernel<<<4096, 256, EM_SMEM>>>();
    fuse_gate_kernel<<<NPOS / 32, 256>>>();
    proj_single3_mma<5><<<NPOS / 64, 256, PJ_SMEM_S3>>>(b_o, out);
}